// round 12
// baseline (speedup 1.0000x reference)
#include <cuda_runtime.h>
#include <cuda_bf16.h>
#include <math.h>
#include <stdint.h>

#define BATCH 2
#define SEQ   2048
#define MODEL 2048
#define NH    32
#define NKV   8
#define HD    64
#define ROWS  (BATCH*SEQ)   // 4096
#define KVW   (NKV*HD)      // 512

typedef unsigned long long u64;
typedef __nv_bfloat16 bf16;

// ---------------- mma.sync helpers -----------------------------------------
__device__ __forceinline__ uint32_t smem_u32(const void* p) {
    uint32_t a;
    asm("{ .reg .u64 t; cvta.to.shared.u64 t, %1; cvt.u32.u64 %0, t; }" : "=r"(a) : "l"(p));
    return a;
}
__device__ __forceinline__ void ldsm4(uint32_t* r, uint32_t addr) {
    asm volatile("ldmatrix.sync.aligned.m8n8.x4.shared.b16 {%0,%1,%2,%3}, [%4];"
                 : "=r"(r[0]), "=r"(r[1]), "=r"(r[2]), "=r"(r[3]) : "r"(addr));
}
__device__ __forceinline__ void mma_bf16(float* d, const uint32_t* a, const uint32_t* b) {
    asm volatile("mma.sync.aligned.m16n8k16.row.col.f32.bf16.bf16.f32 "
                 "{%0,%1,%2,%3}, {%4,%5,%6,%7}, {%8,%9}, {%0,%1,%2,%3};"
                 : "+f"(d[0]), "+f"(d[1]), "+f"(d[2]), "+f"(d[3])
                 : "r"(a[0]), "r"(a[1]), "r"(a[2]), "r"(a[3]), "r"(b[0]), "r"(b[1]));
}
__device__ __forceinline__ void cp16(uint32_t dst, const void* src) {
    asm volatile("cp.async.cg.shared.global [%0], [%1], 16;" :: "r"(dst), "l"(src));
}
#define CP_COMMIT() asm volatile("cp.async.commit_group;" ::: "memory")
#define CP_WAIT0()  asm volatile("cp.async.wait_group 0;" ::: "memory")
#define CP_WAIT1()  asm volatile("cp.async.wait_group 1;" ::: "memory")

// bf16x2 pack/split: lo float -> bits[15:0], hi float -> bits[31:16]
__device__ __forceinline__ uint32_t pkbf2(float lo, float hi) {
    uint32_t r; asm("cvt.rn.bf16x2.f32 %0, %1, %2;" : "=r"(r) : "f"(hi), "f"(lo)); return r;
}
__device__ __forceinline__ float bflo(uint32_t p) { return __uint_as_float(p << 16); }
__device__ __forceinline__ float bfhi(uint32_t p) { return __uint_as_float(p & 0xffff0000u); }
__device__ __forceinline__ void split2(float f0, float f1, uint32_t& hp, uint32_t& lp) {
    hp = pkbf2(f0, f1);
    lp = pkbf2(f0 - bflo(hp), f1 - bfhi(hp));
}

// ---------------- scratch --------------------------------------------------
__device__ float g_cs[(size_t)SEQ * 32 * 2];

__device__ bf16 g_xh[(size_t)ROWS * MODEL];
__device__ bf16 g_xl[(size_t)ROWS * MODEL];
__device__ bf16 g_Qh[(size_t)ROWS * NH * HD];
__device__ bf16 g_Ql[(size_t)ROWS * NH * HD];
__device__ bf16 g_Kh[(size_t)ROWS * KVW];
__device__ bf16 g_Kl[(size_t)ROWS * KVW];
__device__ bf16 g_Vth[(size_t)BATCH * KVW * SEQ];
__device__ bf16 g_Vtl[(size_t)BATCH * KVW * SEQ];
__device__ bf16 g_Yh[(size_t)ROWS * NH * HD];
__device__ bf16 g_Yl[(size_t)ROWS * NH * HD];
__device__ bf16 g_Wqt_h[(size_t)(NH  * HD) * MODEL];
__device__ bf16 g_Wqt_l[(size_t)(NH  * HD) * MODEL];
__device__ bf16 g_Wkt_h[(size_t)KVW * MODEL];
__device__ bf16 g_Wkt_l[(size_t)KVW * MODEL];
__device__ bf16 g_Wvt_h[(size_t)KVW * MODEL];
__device__ bf16 g_Wvt_l[(size_t)KVW * MODEL];
__device__ bf16 g_Wot_h[(size_t)MODEL * (NH * HD)];
__device__ bf16 g_Wot_l[(size_t)MODEL * (NH * HD)];

// ---------------------------------------------------------------------------
// RoPE cos/sin table (fp64 trig once)
// ---------------------------------------------------------------------------
__global__ __launch_bounds__(256)
void rope_table() {
    int i = blockIdx.x * 256 + threadIdx.x;
    if (i >= SEQ * 32) return;
    int d = i & 31;
    int s = i >> 5;
    double inv = exp2(-(double)d * (13.287712379549448882 / 32.0));
    double ang = (double)s * inv;
    double sd, cd;
    sincos(ang, &sd, &cd);
    g_cs[2 * i + 0] = (float)cd;
    g_cs[2 * i + 1] = (float)sd;
}

// ---------------------------------------------------------------------------
// split fp32 -> (hi, lo) bf16  (x only)
// ---------------------------------------------------------------------------
__global__ __launch_bounds__(256)
void split_rows(const float* __restrict__ X, bf16* __restrict__ H,
                bf16* __restrict__ L, int total) {
    int i = blockIdx.x * 256 + threadIdx.x;
    if (i >= total) return;
    float v = X[i];
    bf16 h = __float2bfloat16(v);
    H[i] = h;
    L[i] = __float2bfloat16(v - __bfloat162float(h));
}

// ---------------------------------------------------------------------------
// ALL weight transposes in one launch: z=0 Wq, 1 Wo, 2 Wk, 3 Wv
// ---------------------------------------------------------------------------
__global__ __launch_bounds__(256)
void ts_all(const float* __restrict__ Wq, const float* __restrict__ Wk,
            const float* __restrict__ Wv, const float* __restrict__ Wo) {
    __shared__ float tile[32][33];
    const float* W; bf16 *Th, *Tl; int Kd, Nw, nx;
    switch (blockIdx.z) {
        case 0:  W = Wq; Th = g_Wqt_h; Tl = g_Wqt_l; Kd = MODEL;   Nw = NH * HD; nx = 64; break;
        case 1:  W = Wo; Th = g_Wot_h; Tl = g_Wot_l; Kd = NH * HD; Nw = MODEL;   nx = 64; break;
        case 2:  W = Wk; Th = g_Wkt_h; Tl = g_Wkt_l; Kd = MODEL;   Nw = KVW;     nx = 16; break;
        default: W = Wv; Th = g_Wvt_h; Tl = g_Wvt_l; Kd = MODEL;   Nw = KVW;     nx = 16; break;
    }
    if ((int)blockIdx.x >= nx) return;
    int n0 = blockIdx.x * 32, k0 = blockIdx.y * 32;
    int tx = threadIdx.x & 31, ty = threadIdx.x >> 5;
    #pragma unroll
    for (int j = ty; j < 32; j += 8)
        tile[j][tx] = W[(size_t)(k0 + j) * Nw + n0 + tx];
    __syncthreads();
    #pragma unroll
    for (int j = ty; j < 32; j += 8) {
        float v = tile[tx][j];
        bf16 h = __float2bfloat16(v);
        Th[(size_t)(n0 + j) * Kd + k0 + tx] = h;
        Tl[(size_t)(n0 + j) * Kd + k0 + tx] = __float2bfloat16(v - __bfloat162float(h));
    }
}

// ---------------------------------------------------------------------------
// Split-bf16 tensor-core GEMM core — 128 threads, tile 64x128, 4 CTAs/SM.
// SINGLE-SYNC double-buffered pipeline: load(t+1) issued BEFORE compute(t).
// ---------------------------------------------------------------------------
#define GSTAGE 24576            // A 64x128B (8KB) + B 128x128B (16KB)
#define GEMM_SMEM (2 * GSTAGE)  // 49152

__device__ __forceinline__ void g_load_stage(uint32_t sbase,
                                             const bf16* Ah, const bf16* Al,
                                             const bf16* Bh, const bf16* Bl,
                                             int bm, int bn, int kb, int K, int tid) {
    #pragma unroll
    for (int it = 0; it < 4; it++) {          // A: 64 rows x 8 chunks = 512
        int idx = tid + it * 128;
        int r = idx >> 3, c = idx & 7;
        uint32_t dst = sbase + r * 128 + ((c ^ (r & 7)) << 4);
        const bf16* src = (c < 4 ? Ah : Al) + (size_t)(bm + r) * K + kb * 32 + (c & 3) * 8;
        cp16(dst, src);
    }
    #pragma unroll
    for (int it = 0; it < 8; it++) {          // B: 128 rows x 8 chunks = 1024
        int idx = tid + it * 128;
        int r = idx >> 3, c = idx & 7;
        uint32_t dst = sbase + 8192 + r * 128 + ((c ^ (r & 7)) << 4);
        const bf16* src = (c < 4 ? Bh : Bl) + (size_t)(bn + r) * K + kb * 32 + (c & 3) * 8;
        cp16(dst, src);
    }
}

template<int MODE>
__device__ __forceinline__
void gemm_mma_core(const bf16* __restrict__ Ah, const bf16* __restrict__ Al,
                   const bf16* __restrict__ Bh, const bf16* __restrict__ Bl,
                   float* __restrict__ C, bf16* __restrict__ Ch,
                   bf16* __restrict__ Cl, float rscale,
                   int Nt, int K, int bm, int bn) {
    extern __shared__ char smg[];
    const uint32_t sbase = smem_u32(smg);
    const int tid  = threadIdx.x;
    const int lane = tid & 31;
    const int warp = tid >> 5;            // 0..3
    const int wm   = (warp & 1) * 32;
    const int wn   = (warp >> 1) * 64;

    float acc[2][8][4];
    #pragma unroll
    for (int am = 0; am < 2; am++)
        #pragma unroll
        for (int an = 0; an < 8; an++)
            #pragma unroll
            for (int j = 0; j < 4; j++) acc[am][an][j] = 0.f;

    const int KB = K >> 5;
    g_load_stage(sbase, Ah, Al, Bh, Bl, bm, bn, 0, K, tid); CP_COMMIT();

    const int a_row  = wm + (lane & 15);
    const int a_kh   = (lane >> 4) & 1;
    const int b_n    = wn + (lane & 7) + ((lane >> 4) << 3);
    const int b_kh   = (lane >> 3) & 1;

    for (int t = 0; t < KB; t++) {
        CP_WAIT0();            // load(t) landed
        __syncthreads();       // ...and compute(t-1) done by all warps
        if (t + 1 < KB) {
            g_load_stage(sbase + ((t + 1) & 1) * GSTAGE,
                         Ah, Al, Bh, Bl, bm, bn, t + 1, K, tid);
        }
        CP_COMMIT();

        const uint32_t sA = sbase + (t & 1) * GSTAGE;
        const uint32_t sB = sA + 8192;

        #pragma unroll
        for (int h = 0; h < 2; h++) {
            uint32_t bh[4][4], bl[4][4];
            #pragma unroll
            for (int g = 0; g < 4; g++) {
                int n = b_n + g * 16;
                int ch = h * 2 + b_kh;
                ldsm4(bh[g], sB + n * 128 + (((ch)     ^ (n & 7)) << 4));
                ldsm4(bl[g], sB + n * 128 + (((ch + 4) ^ (n & 7)) << 4));
            }
            #pragma unroll
            for (int am = 0; am < 2; am++) {
                int r  = a_row + am * 16;
                int ch = h * 2 + a_kh;
                uint32_t ah[4], al[4];
                ldsm4(ah, sA + r * 128 + (((ch)     ^ (r & 7)) << 4));
                ldsm4(al, sA + r * 128 + (((ch + 4) ^ (r & 7)) << 4));
                #pragma unroll
                for (int g = 0; g < 4; g++) {
                    mma_bf16(acc[am][2 * g],     ah, &bh[g][0]);
                    mma_bf16(acc[am][2 * g + 1], ah, &bh[g][2]);
                }
                #pragma unroll
                for (int g = 0; g < 4; g++) {
                    mma_bf16(acc[am][2 * g],     al, &bh[g][0]);
                    mma_bf16(acc[am][2 * g + 1], al, &bh[g][2]);
                }
                #pragma unroll
                for (int g = 0; g < 4; g++) {
                    mma_bf16(acc[am][2 * g],     ah, &bl[g][0]);
                    mma_bf16(acc[am][2 * g + 1], ah, &bl[g][2]);
                }
            }
        }
    }

    if (MODE == 0) {
        #pragma unroll
        for (int am = 0; am < 2; am++) {
            int r0 = bm + wm + am * 16 + (lane >> 2);
            #pragma unroll
            for (int an = 0; an < 8; an++) {
                int col = bn + wn + an * 8 + (lane & 3) * 2;
                *(float2*)&C[(size_t)r0 * Nt + col]       = make_float2(acc[am][an][0], acc[am][an][1]);
                *(float2*)&C[(size_t)(r0 + 8) * Nt + col] = make_float2(acc[am][an][2], acc[am][an][3]);
            }
        }
    } else if (MODE == 1) {
        // rope + scale + split epilogue. d (col&31) pairs with d+32 = an+4.
        #pragma unroll
        for (int am = 0; am < 2; am++) {
            int r0 = bm + wm + am * 16 + (lane >> 2);
            #pragma unroll
            for (int rh = 0; rh < 2; rh++) {
                int row = r0 + rh * 8;
                int s   = row & (SEQ - 1);
                #pragma unroll
                for (int an = 0; an < 4; an++) {
                    int col = bn + wn + an * 8 + (lane & 3) * 2;
                    int d0  = col & 31;
                    float2 cs0 = *(const float2*)&g_cs[2 * (s * 32 + d0)];
                    float2 cs1 = *(const float2*)&g_cs[2 * (s * 32 + d0 + 1)];
                    float v0a = acc[am][an][rh * 2],     v0b = acc[am][an][rh * 2 + 1];
                    float v1a = acc[am][an + 4][rh * 2], v1b = acc[am][an + 4][rh * 2 + 1];
                    float loa = (v0a * cs0.x - v1a * cs0.y) * rscale;
                    float lob = (v0b * cs1.x - v1b * cs1.y) * rscale;
                    float hia = (v1a * cs0.x + v0a * cs0.y) * rscale;
                    float hib = (v1b * cs1.x + v0b * cs1.y) * rscale;
                    uint32_t hp, lp;
                    split2(loa, lob, hp, lp);
                    *(uint32_t*)&Ch[(size_t)row * Nt + col] = hp;
                    *(uint32_t*)&Cl[(size_t)row * Nt + col] = lp;
                    split2(hia, hib, hp, lp);
                    *(uint32_t*)&Ch[(size_t)row * Nt + col + 32] = hp;
                    *(uint32_t*)&Cl[(size_t)row * Nt + col + 32] = lp;
                }
            }
        }
    } else {
        // V transpose + split epilogue: out[(b*NKV + c>>6)*64 + (c&63)][s]
        #pragma unroll
        for (int am = 0; am < 2; am++) {
            int r0 = bm + wm + am * 16 + (lane >> 2);
            #pragma unroll
            for (int rh = 0; rh < 2; rh++) {
                int row = r0 + rh * 8;
                int bb  = row >> 11;
                int sl  = row & (SEQ - 1);
                #pragma unroll
                for (int an = 0; an < 8; an++) {
                    int col = bn + wn + an * 8 + (lane & 3) * 2;
                    float va = acc[am][an][rh * 2];
                    float vb = acc[am][an][rh * 2 + 1];
                    size_t o0 = ((size_t)(bb * NKV + (col >> 6)) * 64 + (col & 63)) * SEQ + sl;
                    size_t o1 = o0 + SEQ;
                    bf16 ha = __float2bfloat16(va);
                    Ch[o0] = ha;
                    Cl[o0] = __float2bfloat16(va - __bfloat162float(ha));
                    bf16 hb = __float2bfloat16(vb);
                    Ch[o1] = hb;
                    Cl[o1] = __float2bfloat16(vb - __bfloat162float(hb));
                }
            }
        }
    }
}

__global__ __launch_bounds__(128, 4)
void gemm_mma(const bf16* __restrict__ Ah, const bf16* __restrict__ Al,
              const bf16* __restrict__ Bh, const bf16* __restrict__ Bl,
              float* __restrict__ C, int Nt, int K) {
    gemm_mma_core<0>(Ah, Al, Bh, Bl, C, nullptr, nullptr, 0.f,
                     Nt, K, blockIdx.y * 64, blockIdx.x * 128);
}

__global__ __launch_bounds__(128, 4)
void gemm_mma_rope(const bf16* __restrict__ Ah, const bf16* __restrict__ Al,
                   const bf16* __restrict__ Bh, const bf16* __restrict__ Bl,
                   bf16* __restrict__ Ch, bf16* __restrict__ Cl,
                   float rscale, int Nt, int K) {
    gemm_mma_core<1>(Ah, Al, Bh, Bl, nullptr, Ch, Cl, rscale,
                     Nt, K, blockIdx.y * 64, blockIdx.x * 128);
}

// K (z=0, rope+split) and V (z=1, transpose+split) in one launch
__global__ __launch_bounds__(128, 4)
void gemm_mma_kv(const bf16* __restrict__ Ah, const bf16* __restrict__ Al,
                 const bf16* __restrict__ Bkh, const bf16* __restrict__ Bkl,
                 const bf16* __restrict__ Bvh, const bf16* __restrict__ Bvl,
                 bf16* __restrict__ Kh, bf16* __restrict__ Kl,
                 bf16* __restrict__ Vth, bf16* __restrict__ Vtl, int Nt, int K) {
    if (blockIdx.z == 0)
        gemm_mma_core<1>(Ah, Al, Bkh, Bkl, nullptr, Kh, Kl, 1.0f,
                         Nt, K, blockIdx.y * 64, blockIdx.x * 128);
    else
        gemm_mma_core<2>(Ah, Al, Bvh, Bvl, nullptr, Vth, Vtl, 0.f,
                         Nt, K, blockIdx.y * 64, blockIdx.x * 128);
}

// ---------------------------------------------------------------------------
// Tensor-core flash attention — single-sync double buffer per KV tile.
// ---------------------------------------------------------------------------
#define QSTR 144
#define FA_STG_SZ 36864
#define FA_SQH 36864
#define FA_SQL 55296
#define FA_SMEM 73728

__device__ __forceinline__
void fa_load_kv(uint32_t sb, const bf16* __restrict__ Khp, const bf16* __restrict__ Klp,
                const bf16* __restrict__ Vhp, const bf16* __restrict__ Vlp,
                size_t krow0, int s0, int tid) {
    #pragma unroll
    for (int i = 0; i < 2; i++) {
        int idx = tid + i * 256;
        int r = idx >> 3, c = idx & 7;
        uint32_t so = r * QSTR + c * 16;
        cp16(sb + so,         Khp + (krow0 + r) * KVW + c * 8);
        cp16(sb + 9216 + so,  Klp + (krow0 + r) * KVW + c * 8);
        cp16(sb + 18432 + so, Vhp + (size_t)r * SEQ + s0 + c * 8);
        cp16(sb + 27648 + so, Vlp + (size_t)r * SEQ + s0 + c * 8);
    }
}

__global__ __launch_bounds__(256, 2)
void flashattn_mma(const bf16* __restrict__ Qh, const bf16* __restrict__ Ql,
                   const bf16* __restrict__ Kh, const bf16* __restrict__ Kl,
                   const bf16* __restrict__ Vth, const bf16* __restrict__ Vtl,
                   bf16* __restrict__ Yh, bf16* __restrict__ Yl) {
    extern __shared__ char sm[];
    const uint32_t base = smem_u32(sm);
    const int tid  = threadIdx.x;
    const int lane = tid & 31;
    const int warp = tid >> 5;
    const int qt   = gridDim.x - 1 - blockIdx.x;
    const int h    = blockIdx.y;
    const int b    = blockIdx.z;
    const int kvh  = h >> 2;
    const int wm   = warp * 16;

    const bf16* Khp = Kh + kvh * 64;
    const bf16* Klp = Kl + kvh * 64;
    const bf16* Vhp = Vth + (size_t)((b * NKV + kvh) * 64) * SEQ;
    const bf16* Vlp = Vtl + (size_t)((b * NKV + kvh) * 64) * SEQ;
    const int njt = 2 * qt + 2;

    // ---- Q cp.async into stage-1 footprint (group 0, waited first) ----
    {
        size_t qrow0 = (size_t)(b * SEQ + qt * 128);
        int hoff = h * HD;
        #pragma unroll
        for (int i = 0; i < 4; i++) {
            int idx = tid + i * 256;
            int r = idx >> 3, c = idx & 7;
            cp16(base + FA_SQH + r * QSTR + c * 16, Qh + (qrow0 + r) * (NH * HD) + hoff + c * 8);
            cp16(base + FA_SQL + r * QSTR + c * 16, Ql + (qrow0 + r) * (NH * HD) + hoff + c * 8);
        }
    }
    CP_COMMIT();

    // ---- prefetch first KV tile into stage0 (group 1) ----
    fa_load_kv(base, Khp, Klp, Vhp, Vlp, (size_t)b * SEQ, 0, tid);
    CP_COMMIT();

    CP_WAIT1();        // Q group done (KV0 may still be in flight)
    __syncthreads();

    // ---- Q fragments to registers (Q smem region becomes stage1 afterwards) --
    const int a_row = wm + (lane & 15);
    const int a_kh  = (lane >> 4) & 1;
    uint32_t qh[4][4], ql[4][4];
    #pragma unroll
    for (int kc = 0; kc < 4; kc++) {
        ldsm4(qh[kc], base + FA_SQH + a_row * QSTR + kc * 32 + a_kh * 16);
        ldsm4(ql[kc], base + FA_SQL + a_row * QSTR + kc * 32 + a_kh * 16);
    }

    const int b_n  = (lane & 7) + ((lane >> 4) << 3);
    const int b_kh = (lane >> 3) & 1;

    float m0 = -INFINITY, m1 = -INFINITY, l0 = 0.f, l1 = 0.f;
    float oa[8][4];
    #pragma unroll
    for (int f = 0; f < 8; f++)
        #pragma unroll
        for (int j = 0; j < 4; j++) oa[f][j] = 0.f;

    for (int jt = 0; jt < njt; jt++) {
        CP_WAIT0();            // KV(jt) landed
        __syncthreads();       // ...and compute(jt-1) done by all (Q frags read at jt=0)
        if (jt + 1 < njt) {
            fa_load_kv(base + ((jt + 1) & 1) * FA_STG_SZ,
                       Khp, Klp, Vhp, Vlp,
                       (size_t)b * SEQ + (jt + 1) * 64, (jt + 1) * 64, tid);
        }
        CP_COMMIT();

        const uint32_t stg = base + (jt & 1) * FA_STG_SZ;

        // ---- S = Q @ K^T (base-2 scaled) ----
        float sa[8][4];
        #pragma unroll
        for (int f = 0; f < 8; f++)
            #pragma unroll
            for (int j = 0; j < 4; j++) sa[f][j] = 0.f;

        #pragma unroll
        for (int kc = 0; kc < 4; kc++) {
            #pragma unroll
            for (int g = 0; g < 4; g++) {
                uint32_t kh4[4], kl4[4];
                ldsm4(kh4, stg + (b_n + g * 16) * QSTR + kc * 32 + b_kh * 16);
                ldsm4(kl4, stg + 9216 + (b_n + g * 16) * QSTR + kc * 32 + b_kh * 16);
                mma_bf16(sa[2 * g],     qh[kc], &kh4[0]);
                mma_bf16(sa[2 * g + 1], qh[kc], &kh4[2]);
                mma_bf16(sa[2 * g],     ql[kc], &kh4[0]);
                mma_bf16(sa[2 * g + 1], ql[kc], &kh4[2]);
                mma_bf16(sa[2 * g],     qh[kc], &kl4[0]);
                mma_bf16(sa[2 * g + 1], qh[kc], &kl4[2]);
            }
        }

        // ---- causal mask ----
        if (jt * 64 + 63 > qt * 128) {
            int r0g = qt * 128 + wm + (lane >> 2);
            int r1g = r0g + 8;
            #pragma unroll
            for (int f = 0; f < 8; f++) {
                int c0 = jt * 64 + f * 8 + (lane & 3) * 2;
                if (c0 > r0g)     sa[f][0] = -INFINITY;
                if (c0 + 1 > r0g) sa[f][1] = -INFINITY;
                if (c0 > r1g)     sa[f][2] = -INFINITY;
                if (c0 + 1 > r1g) sa[f][3] = -INFINITY;
            }
        }

        // ---- online softmax (base 2) ----
        float rm0 = -INFINITY, rm1 = -INFINITY;
        #pragma unroll
        for (int f = 0; f < 8; f++) {
            rm0 = fmaxf(rm0, fmaxf(sa[f][0], sa[f][1]));
            rm1 = fmaxf(rm1, fmaxf(sa[f][2], sa[f][3]));
        }
        rm0 = fmaxf(rm0, __shfl_xor_sync(0xffffffffu, rm0, 1));
        rm0 = fmaxf(rm0, __shfl_xor_sync(0xffffffffu, rm0, 2));
        rm1 = fmaxf(rm1, __shfl_xor_sync(0xffffffffu, rm1, 1));
        rm1 = fmaxf(rm1, __shfl_xor_sync(0xffffffffu, rm1, 2));

        float mn0 = fmaxf(m0, rm0), mn1 = fmaxf(m1, rm1);
        float f0 = exp2f(m0 - mn0), f1 = exp2f(m1 - mn1);
        float rs0 = 0.f, rs1 = 0.f;
        #pragma unroll
        for (int f = 0; f < 8; f++) {
            sa[f][0] = exp2f(sa[f][0] - mn0);
            sa[f][1] = exp2f(sa[f][1] - mn0);
            sa[f][2] = exp2f(sa[f][2] - mn1);
            sa[f][3] = exp2f(sa[f][3] - mn1);
            rs0 += sa[f][0] + sa[f][1];
            rs1 += sa[f][2] + sa[f][3];
        }
        rs0 += __shfl_xor_sync(0xffffffffu, rs0, 1);
        rs0 += __shfl_xor_sync(0xffffffffu, rs0, 2);
        rs1 += __shfl_xor_sync(0xffffffffu, rs1, 1);
        rs1 += __shfl_xor_sync(0xffffffffu, rs1, 2);

        l0 = l0 * f0 + rs0;  m0 = mn0;
        l1 = l1 * f1 + rs1;  m1 = mn1;
        #pragma unroll
        for (int f = 0; f < 8; f++) {
            oa[f][0] *= f0; oa[f][1] *= f0;
            oa[f][2] *= f1; oa[f][3] *= f1;
        }

        // ---- O += P @ V ----
        #pragma unroll
        for (int kc = 0; kc < 4; kc++) {
            uint32_t ah[4], al[4];
            split2(sa[2 * kc][0],     sa[2 * kc][1],     ah[0], al[0]);
            split2(sa[2 * kc][2],     sa[2 * kc][3],     ah[1], al[1]);
            split2(sa[2 * kc + 1][0], sa[2 * kc + 1][1], ah[2], al[2]);
            split2(sa[2 * kc + 1][2], sa[2 * kc + 1][3], ah[3], al[3]);
            #pragma unroll
            for (int g = 0; g < 4; g++) {
                uint32_t vh4[4], vl4[4];
                ldsm4(vh4, stg + 18432 + (b_n + g * 16) * QSTR + kc * 32 + b_kh * 16);
                ldsm4(vl4, stg + 27648 + (b_n + g * 16) * QSTR + kc * 32 + b_kh * 16);
                mma_bf16(oa[2 * g],     ah, &vh4[0]);
                mma_bf16(oa[2 * g + 1], ah, &vh4[2]);
                mma_bf16(oa[2 * g],     al, &vh4[0]);
                mma_bf16(oa[2 * g + 1], al, &vh4[2]);
                mma_bf16(oa[2 * g],     ah, &vl4[0]);
                mma_bf16(oa[2 * g + 1], ah, &vl4[2]);
            }
        }
    }

    // ---- epilogue: normalize, split, write Yh/Yl ----
    float inv0 = 1.f / l0, inv1 = 1.f / l1;
    size_t row0 = (size_t)(b * SEQ + qt * 128 + wm + (lane >> 2));
    #pragma unroll
    for (int f = 0; f < 8; f++) {
        int col = h * HD + f * 8 + (lane & 3) * 2;
        uint32_t hp, lp;
        split2(oa[f][0] * inv0, oa[f][1] * inv0, hp, lp);
        *(uint32_t*)&Yh[row0 * (NH * HD) + col] = hp;
        *(uint32_t*)&Yl[row0 * (NH * HD) + col] = lp;
        split2(oa[f][2] * inv1, oa[f][3] * inv1, hp, lp);
        *(uint32_t*)&Yh[(row0 + 8) * (NH * HD) + col] = hp;
        *(uint32_t*)&Yl[(row0 + 8) * (NH * HD) + col] = lp;
    }
}

// ---------------------------------------------------------------------------
extern "C" void kernel_launch(void* const* d_in, const int* in_sizes, int n_in,
                              void* d_out, int out_size) {
    const float* x  = (const float*)d_in[0];
    const float* Wq = (const float*)d_in[1];
    const float* Wk = (const float*)d_in[2];
    const float* Wv = (const float*)d_in[3];
    const float* Wo = (const float*)d_in[4];
    float* out = (float*)d_out;

    bf16 *xh, *xl, *Qh, *Ql, *Kh, *Kl, *Vth, *Vtl, *Yh, *Yl;
    bf16 *Wqh, *Wql, *Wkh, *Wkl, *Wvh, *Wvl, *Woh, *Wol;
    cudaGetSymbolAddress((void**)&xh, g_xh);   cudaGetSymbolAddress((void**)&xl, g_xl);
    cudaGetSymbolAddress((void**)&Qh, g_Qh);   cudaGetSymbolAddress((void**)&Ql, g_Ql);
    cudaGetSymbolAddress((void**)&Kh, g_Kh);   cudaGetSymbolAddress((void**)&Kl, g_Kl);
    cudaGetSymbolAddress((void**)&Vth, g_Vth); cudaGetSymbolAddress((void**)&Vtl, g_Vtl);
    cudaGetSymbolAddress((void**)&Yh, g_Yh);   cudaGetSymbolAddress((void**)&Yl, g_Yl);
    cudaGetSymbolAddress((void**)&Wqh, g_Wqt_h); cudaGetSymbolAddress((void**)&Wql, g_Wqt_l);
    cudaGetSymbolAddress((void**)&Wkh, g_Wkt_h); cudaGetSymbolAddress((void**)&Wkl, g_Wkt_l);
    cudaGetSymbolAddress((void**)&Wvh, g_Wvt_h); cudaGetSymbolAddress((void**)&Wvl, g_Wvt_l);
    cudaGetSymbolAddress((void**)&Woh, g_Wot_h); cudaGetSymbolAddress((void**)&Wol, g_Wot_l);

    dim3 blk(256);
    dim3 gblk(128);
    const float QSC = 0.125f * 1.4426950408889634f;   // 1/sqrt(64) * log2(e)

    rope_table<<<(SEQ * 32 + 255) / 256, blk>>>();
    int totx = ROWS * MODEL;
    split_rows<<<(totx + 255) / 256, blk>>>(x, xh, xl, totx);
    ts_all<<<dim3(64, 64, 4), blk>>>(Wq, Wk, Wv, Wo);

    cudaFuncSetAttribute(gemm_mma, cudaFuncAttributeMaxDynamicSharedMemorySize, GEMM_SMEM);
    cudaFuncSetAttribute(gemm_mma_rope, cudaFuncAttributeMaxDynamicSharedMemorySize, GEMM_SMEM);
    cudaFuncSetAttribute(gemm_mma_kv, cudaFuncAttributeMaxDynamicSharedMemorySize, GEMM_SMEM);

    // Q projection with fused rope+scale+split epilogue (64x128 tiles)
    gemm_mma_rope<<<dim3((NH * HD) / 128, ROWS / 64), gblk, GEMM_SMEM>>>(
        xh, xl, Wqh, Wql, Qh, Ql, QSC, NH * HD, MODEL);
    // K (rope+split) and V (transpose+split)
    gemm_mma_kv<<<dim3(KVW / 128, ROWS / 64, 2), gblk, GEMM_SMEM>>>(
        xh, xl, Wkh, Wkl, Wvh, Wvl, Kh, Kl, Vth, Vtl, KVW, MODEL);

    // flash attention
    cudaFuncSetAttribute(flashattn_mma, cudaFuncAttributeMaxDynamicSharedMemorySize, FA_SMEM);
    flashattn_mma<<<dim3(SEQ / 128, NH, BATCH), blk, FA_SMEM>>>(
        Qh, Ql, Kh, Kl, Vth, Vtl, Yh, Yl);

    // output projection
    gemm_mma<<<dim3(MODEL / 128, ROWS / 64), gblk, GEMM_SMEM>>>(
        Yh, Yl, Woh, Wol, out, MODEL, MODEL);
}